// round 1
// baseline (speedup 1.0000x reference)
#include <cuda_runtime.h>

// Problem constants
#define BB      512      // batch
#define INU     8        // in_units (k)
#define INCH    1152     // in_channels (i)
#define NU      10       // num_units (j)
#define US      16       // unit_size (u)
#define JU      160      // NU*US
#define KI      9216     // INU*INCH  (contraction dim for s-GEMM)
#define BETA    1.45f
#define KSPLIT  36
#define KCHUNK  256      // KI / KSPLIT

// Scratch (device globals -- no allocation allowed)
__device__ float g_Wt[KI * JU];            // Wt[k*1152+i][j*16+u] = W[i,j,u,k]
__device__ float g_Wc[KI * JU];            // c-scaled Wt
__device__ float g_G [KI * JU];            // G = x^T @ v
__device__ float g_spart[KSPLIT * BB * JU];
__device__ float g_s[BB * JU];
__device__ float g_v[BB * JU];
__device__ float g_b[INCH * NU];
__device__ float g_c[INCH * NU];

// ---------------------------------------------------------------------------
__global__ void zero_b_k() {
    int idx = blockIdx.x * blockDim.x + threadIdx.x;
    if (idx < INCH * NU) g_b[idx] = 0.0f;
}

// Wt[(k*INCH+i)*JU + j*US+u] = W[((i*NU+j)*US+u)*INU + k]
__global__ void transposeW_k(const float* __restrict__ W) {
    int idx = blockIdx.x * blockDim.x + threadIdx.x;
    if (idx >= KI * JU) return;
    int ki = idx / JU;
    int ju = idx - ki * JU;
    int k = ki / INCH;
    int i = ki - k * INCH;
    int j = ju >> 4;
    int u = ju & 15;
    g_Wt[idx] = W[((i * NU + j) * US + u) * INU + k];
}

// softmax over i (axis 0) for each column j of g_b (INCH x NU)
__global__ void softmax_k() {
    int j = blockIdx.x;                  // 0..9
    __shared__ float red[128];
    int t = threadIdx.x;
    float mx = -1e30f;
    for (int i = t; i < INCH; i += 128) mx = fmaxf(mx, g_b[i * NU + j]);
    red[t] = mx; __syncthreads();
    for (int o = 64; o > 0; o >>= 1) {
        if (t < o) red[t] = fmaxf(red[t], red[t + o]);
        __syncthreads();
    }
    mx = red[0]; __syncthreads();
    float sum = 0.0f;
    for (int i = t; i < INCH; i += 128) sum += __expf(g_b[i * NU + j] - mx);
    red[t] = sum; __syncthreads();
    for (int o = 64; o > 0; o >>= 1) {
        if (t < o) red[t] += red[t + o];
        __syncthreads();
    }
    float inv = 1.0f / red[0];
    for (int i = t; i < INCH; i += 128)
        g_c[i * NU + j] = __expf(g_b[i * NU + j] - mx) * inv;
}

// Wc[ki][ju] = c[ki % INCH][ju>>4] * Wt[ki][ju]
__global__ void scaleW_k() {
    int idx = blockIdx.x * blockDim.x + threadIdx.x;
    if (idx >= KI * JU) return;
    int ki = idx / JU;
    int ju = idx - ki * JU;
    int i = ki % INCH;
    int j = ju >> 4;
    g_Wc[idx] = g_c[i * NU + j] * g_Wt[idx];
}

// GEMM1: s_part = x(512 x 9216) @ Wc(9216 x 160), split-K over KSPLIT chunks.
// Block tile 64(M) x 160(N), 256 threads, micro-tile 4x10.
__global__ __launch_bounds__(256) void gemm1_k(const float* __restrict__ x) {
    __shared__ float As[16][64];
    __shared__ float Bs[16][160];
    const int m0 = blockIdx.x * 64;
    const int kbase0 = blockIdx.y * KCHUNK;
    const int tid = threadIdx.x;
    const int trow = tid >> 4;      // 0..15
    const int tcol = tid & 15;      // 0..15

    float acc[4][10];
#pragma unroll
    for (int r = 0; r < 4; r++)
#pragma unroll
        for (int c = 0; c < 10; c++) acc[r][c] = 0.0f;

    const int aRow = tid >> 2;            // 0..63
    const int aCol = (tid & 3) * 4;       // 0,4,8,12

    for (int ks = 0; ks < KCHUNK; ks += 16) {
        const int kb = kbase0 + ks;
        // load A tile (64 x 16), transposed into As[kk][m]
        {
            float4 av = *reinterpret_cast<const float4*>(&x[(m0 + aRow) * KI + kb + aCol]);
            As[aCol + 0][aRow] = av.x;
            As[aCol + 1][aRow] = av.y;
            As[aCol + 2][aRow] = av.z;
            As[aCol + 3][aRow] = av.w;
        }
        // load B tile (16 x 160)
#pragma unroll
        for (int l = 0; l < 10; l++) {
            int idx = tid + l * 256;
            int kk = idx / 160;
            int n  = idx - kk * 160;
            Bs[kk][n] = g_Wc[(kb + kk) * JU + n];
        }
        __syncthreads();
#pragma unroll
        for (int kk = 0; kk < 16; kk++) {
            float a[4];
#pragma unroll
            for (int r = 0; r < 4; r++) a[r] = As[kk][trow * 4 + r];
            float bb[10];
#pragma unroll
            for (int c = 0; c < 10; c++) bb[c] = Bs[kk][tcol * 10 + c];
#pragma unroll
            for (int r = 0; r < 4; r++)
#pragma unroll
                for (int c = 0; c < 10; c++) acc[r][c] = fmaf(a[r], bb[c], acc[r][c]);
        }
        __syncthreads();
    }

    float* out = &g_spart[blockIdx.y * (BB * JU)];
#pragma unroll
    for (int r = 0; r < 4; r++)
#pragma unroll
        for (int c = 0; c < 10; c++)
            out[(m0 + trow * 4 + r) * JU + tcol * 10 + c] = acc[r][c];
}

// reduce split-K partials: s = sum over KSPLIT of s_part
__global__ void reduceS_k() {
    int idx = blockIdx.x * blockDim.x + threadIdx.x;
    if (idx >= BB * JU) return;
    float acc = 0.0f;
#pragma unroll
    for (int ks = 0; ks < KSPLIT; ks++) acc += g_spart[ks * (BB * JU) + idx];
    g_s[idx] = acc;
}

// squash: mag_sq over j (num_units axis). Writes g_v, optionally also d_out.
__global__ void squash_k(float* __restrict__ out, int writeOut) {
    int idx = blockIdx.x * blockDim.x + threadIdx.x;   // (b,u) pairs: 512*16
    if (idx >= BB * US) return;
    int b = idx >> 4;
    int u = idx & 15;
    float sv[NU];
    float msq = 0.0f;
#pragma unroll
    for (int j = 0; j < NU; j++) {
        sv[j] = g_s[b * JU + j * US + u];
        msq += sv[j] * sv[j];
    }
    float mag = sqrtf(msq);
    float sc = msq / ((BETA + msq) * mag);
    if (writeOut) {
#pragma unroll
        for (int j = 0; j < NU; j++) out[b * JU + j * US + u] = sc * sv[j];
    } else {
#pragma unroll
        for (int j = 0; j < NU; j++) g_v[b * JU + j * US + u] = sc * sv[j];
    }
}

// GEMM2: G(9216 x 160) = x^T(9216 x 512) @ v(512 x 160)
// Block tile 64(M over ki) x 160(N), K = 512 (batch), 256 threads, 4x10 micro.
__global__ __launch_bounds__(256) void gemm2_k(const float* __restrict__ x) {
    __shared__ float As[16][64];
    __shared__ float Bs[16][160];
    const int m0 = blockIdx.x * 64;     // over KI
    const int tid = threadIdx.x;
    const int trow = tid >> 4;
    const int tcol = tid & 15;

    float acc[4][10];
#pragma unroll
    for (int r = 0; r < 4; r++)
#pragma unroll
        for (int c = 0; c < 10; c++) acc[r][c] = 0.0f;

    for (int kb = 0; kb < BB; kb += 16) {
        // A tile: As[kk][m] = x[(kb+kk)*KI + m0+m]  (already [kk][m], coalesced on m)
#pragma unroll
        for (int l = 0; l < 4; l++) {
            int idx = tid + l * 256;      // 0..1023
            int kk = idx >> 6;
            int m  = idx & 63;
            As[kk][m] = x[(kb + kk) * KI + m0 + m];
        }
#pragma unroll
        for (int l = 0; l < 10; l++) {
            int idx = tid + l * 256;
            int kk = idx / 160;
            int n  = idx - kk * 160;
            Bs[kk][n] = g_v[(kb + kk) * JU + n];
        }
        __syncthreads();
#pragma unroll
        for (int kk = 0; kk < 16; kk++) {
            float a[4];
#pragma unroll
            for (int r = 0; r < 4; r++) a[r] = As[kk][trow * 4 + r];
            float bb[10];
#pragma unroll
            for (int c = 0; c < 10; c++) bb[c] = Bs[kk][tcol * 10 + c];
#pragma unroll
            for (int r = 0; r < 4; r++)
#pragma unroll
                for (int c = 0; c < 10; c++) acc[r][c] = fmaf(a[r], bb[c], acc[r][c]);
        }
        __syncthreads();
    }
#pragma unroll
    for (int r = 0; r < 4; r++)
#pragma unroll
        for (int c = 0; c < 10; c++)
            g_G[(m0 + trow * 4 + r) * JU + tcol * 10 + c] = acc[r][c];
}

// b[i,j] = (1/B) * sum_{k,u} Wt[(k*INCH+i)*JU + j*US+u] * G[same]
__global__ void bupdate_k() {
    int gw = (blockIdx.x * blockDim.x + threadIdx.x) >> 5;
    int lane = threadIdx.x & 31;
    if (gw >= INCH * NU) return;
    int i = gw / NU;
    int j = gw - i * NU;
    float acc = 0.0f;
#pragma unroll
    for (int p = lane; p < 128; p += 32) {   // p = k*16 + u
        int k = p >> 4;
        int u = p & 15;
        int idx = (k * INCH + i) * JU + j * US + u;
        acc += g_Wt[idx] * g_G[idx];
    }
#pragma unroll
    for (int o = 16; o > 0; o >>= 1) acc += __shfl_xor_sync(0xffffffffu, acc, o);
    if (lane == 0) g_b[i * NU + j] = acc * (1.0f / (float)BB);
}

// ---------------------------------------------------------------------------
extern "C" void kernel_launch(void* const* d_in, const int* in_sizes, int n_in,
                              void* d_out, int out_size) {
    const float* x = (const float*)d_in[0];
    const float* W = (const float*)d_in[1];
    // safety: identify by size (x has 4.7M elems, W 1.47M)
    if (n_in >= 2 && in_sizes[0] == INCH * NU * US * INU) {
        const float* t = x; x = W; W = t;
    }
    float* out = (float*)d_out;

    zero_b_k<<<(INCH * NU + 255) / 256, 256>>>();
    transposeW_k<<<(KI * JU) / 256, 256>>>(W);

    for (int t = 0; t < 3; t++) {
        softmax_k<<<NU, 128>>>();
        scaleW_k<<<(KI * JU) / 256, 256>>>();
        gemm1_k<<<dim3(BB / 64, KSPLIT), 256>>>(x);
        reduceS_k<<<(BB * JU) / 256, 256>>>();
        squash_k<<<(BB * US) / 256, 256>>>(out, t == 2 ? 1 : 0);
        if (t < 2) {
            gemm2_k<<<KI / 64, 256>>>(x);
            bupdate_k<<<(INCH * NU * 32) / 256, 256>>>();
        }
    }
}

// round 2
// speedup vs baseline: 1.3188x; 1.3188x over previous
#include <cuda_runtime.h>

// Problem constants
#define BB      512      // batch
#define INU     8        // in_units (k)
#define INCH    1152     // in_channels (i)
#define NU      10       // num_units (j)
#define US      16       // unit_size (u)
#define JU      160      // NU*US
#define KI      9216     // INU*INCH  (contraction dim for s-GEMM)
#define BETA    1.45f
#define KSPLIT  72
#define KCHUNK  128      // KI / KSPLIT
#define MT      128      // gemm M tile

// Scratch (device globals -- no allocation allowed)
__device__ float g_Wt[KI * JU];              // Wt[k*1152+i][j*16+u] = W[i,j,u,k]
__device__ float g_Gpart[2][KI * JU];        // split-batch partials of G = x^T @ v
__device__ float g_spart[KSPLIT * BB * JU];
__device__ float g_s[BB * JU];
__device__ float g_v[BB * JU];
__device__ float g_b[INCH * NU];
__device__ float g_c[INCH * NU];

// ---- packed fp32x2 helpers (Blackwell FFMA2) -------------------------------
__device__ __forceinline__ unsigned long long pk2(float v) {
    unsigned long long r;
    asm("mov.b64 %0, {%1, %1};" : "=l"(r) : "f"(v));
    return r;
}
__device__ __forceinline__ void ffma2(unsigned long long& d,
                                      unsigned long long a, unsigned long long b) {
    asm("fma.rn.f32x2 %0, %1, %2, %0;" : "+l"(d) : "l"(a), "l"(b));
}

// ---------------------------------------------------------------------------
__global__ void zero_b_k() {
    int idx = blockIdx.x * blockDim.x + threadIdx.x;
    if (idx < INCH * NU) g_b[idx] = 0.0f;
}

// Wt[(k*INCH+i)*JU + ju] = W[(i*JU+ju)*INU + k]; coalesced reads, 8 coalesced store streams
__global__ void transposeW_k(const float* __restrict__ W) {
    int idx = blockIdx.x * blockDim.x + threadIdx.x;   // over INCH*JU
    if (idx >= INCH * JU) return;
    int i = idx / JU;
    int ju = idx - i * JU;
    float4 w0 = *reinterpret_cast<const float4*>(&W[idx * 8]);
    float4 w1 = *reinterpret_cast<const float4*>(&W[idx * 8 + 4]);
    g_Wt[(0 * INCH + i) * JU + ju] = w0.x;
    g_Wt[(1 * INCH + i) * JU + ju] = w0.y;
    g_Wt[(2 * INCH + i) * JU + ju] = w0.z;
    g_Wt[(3 * INCH + i) * JU + ju] = w0.w;
    g_Wt[(4 * INCH + i) * JU + ju] = w1.x;
    g_Wt[(5 * INCH + i) * JU + ju] = w1.y;
    g_Wt[(6 * INCH + i) * JU + ju] = w1.z;
    g_Wt[(7 * INCH + i) * JU + ju] = w1.w;
}

// softmax over i (axis 0) for each column j of g_b (INCH x NU)
__global__ void softmax_k() {
    int j = blockIdx.x;                  // 0..9
    __shared__ float red[128];
    int t = threadIdx.x;
    float mx = -1e30f;
    for (int i = t; i < INCH; i += 128) mx = fmaxf(mx, g_b[i * NU + j]);
    red[t] = mx; __syncthreads();
    for (int o = 64; o > 0; o >>= 1) {
        if (t < o) red[t] = fmaxf(red[t], red[t + o]);
        __syncthreads();
    }
    mx = red[0]; __syncthreads();
    float sum = 0.0f;
    for (int i = t; i < INCH; i += 128) sum += __expf(g_b[i * NU + j] - mx);
    red[t] = sum; __syncthreads();
    for (int o = 64; o > 0; o >>= 1) {
        if (t < o) red[t] += red[t + o];
        __syncthreads();
    }
    float inv = 1.0f / red[0];
    for (int i = t; i < INCH; i += 128)
        g_c[i * NU + j] = __expf(g_b[i * NU + j] - mx) * inv;
}

// GEMM1: s_part = x(512 x 9216) @ (c⊙Wt)(9216 x 160), split-K over KSPLIT chunks.
// Block tile 128(M) x 160(N), 256 threads, micro-tile 8x10, FFMA2 packed pairs.
__global__ __launch_bounds__(256, 2) void gemm1_k(const float* __restrict__ x) {
    __shared__ float As[16][MT];
    __shared__ float Bs[16][JU];
    const int m0 = blockIdx.x * MT;
    const int kbase0 = blockIdx.y * KCHUNK;
    const int tid = threadIdx.x;
    const int trow = tid >> 4;      // 0..15
    const int tcol = tid & 15;      // 0..15

    unsigned long long acc[8][5];
#pragma unroll
    for (int r = 0; r < 8; r++)
#pragma unroll
        for (int c = 0; c < 5; c++) acc[r][c] = 0ULL;

    const int aRow = tid >> 1;            // 0..127
    const int aCol = (tid & 1) * 8;       // 0 or 8

    for (int ks = 0; ks < KCHUNK; ks += 16) {
        const int kb = kbase0 + ks;
        // A tile (128 x 16), transposed into As[kk][m]
        {
            const float* ap = &x[(m0 + aRow) * KI + kb + aCol];
            float4 a0 = *reinterpret_cast<const float4*>(ap);
            float4 a1 = *reinterpret_cast<const float4*>(ap + 4);
            As[aCol + 0][aRow] = a0.x;
            As[aCol + 1][aRow] = a0.y;
            As[aCol + 2][aRow] = a0.z;
            As[aCol + 3][aRow] = a0.w;
            As[aCol + 4][aRow] = a1.x;
            As[aCol + 5][aRow] = a1.y;
            As[aCol + 6][aRow] = a1.z;
            As[aCol + 7][aRow] = a1.w;
        }
        // B tile (16 x 160) with fused c-scaling
#pragma unroll
        for (int l = 0; l < 10; l++) {
            int idx = tid + l * 256;
            int kk = idx / 160;
            int n  = idx - kk * 160;
            int ki = kb + kk;
            int i  = ki % INCH;
            Bs[kk][n] = g_c[i * NU + (n >> 4)] * g_Wt[ki * JU + n];
        }
        __syncthreads();
#pragma unroll
        for (int kk = 0; kk < 16; kk++) {
            float4 a0 = *reinterpret_cast<const float4*>(&As[kk][trow * 8]);
            float4 a1 = *reinterpret_cast<const float4*>(&As[kk][trow * 8 + 4]);
            unsigned long long ap[8];
            ap[0] = pk2(a0.x); ap[1] = pk2(a0.y); ap[2] = pk2(a0.z); ap[3] = pk2(a0.w);
            ap[4] = pk2(a1.x); ap[5] = pk2(a1.y); ap[6] = pk2(a1.z); ap[7] = pk2(a1.w);
            unsigned long long bp[5];
#pragma unroll
            for (int c = 0; c < 5; c++)
                bp[c] = *reinterpret_cast<const unsigned long long*>(&Bs[kk][tcol * 10 + 2 * c]);
#pragma unroll
            for (int r = 0; r < 8; r++)
#pragma unroll
                for (int c = 0; c < 5; c++) ffma2(acc[r][c], ap[r], bp[c]);
        }
        __syncthreads();
    }

    float* out = &g_spart[blockIdx.y * (BB * JU)];
#pragma unroll
    for (int r = 0; r < 8; r++)
#pragma unroll
        for (int c = 0; c < 5; c++)
            *reinterpret_cast<unsigned long long*>(
                &out[(m0 + trow * 8 + r) * JU + tcol * 10 + 2 * c]) = acc[r][c];
}

// reduce split-K partials: s = sum over KSPLIT of s_part  (float4 vectorized)
__global__ void reduceS_k() {
    int idx = blockIdx.x * blockDim.x + threadIdx.x;   // over BB*JU/4
    if (idx >= BB * JU / 4) return;
    float4 acc = make_float4(0.f, 0.f, 0.f, 0.f);
#pragma unroll
    for (int ks = 0; ks < KSPLIT; ks++) {
        float4 v = *reinterpret_cast<const float4*>(&g_spart[ks * (BB * JU) + idx * 4]);
        acc.x += v.x; acc.y += v.y; acc.z += v.z; acc.w += v.w;
    }
    *reinterpret_cast<float4*>(&g_s[idx * 4]) = acc;
}

// squash: mag_sq over j (num_units axis). Writes g_v, optionally also d_out.
__global__ void squash_k(float* __restrict__ out, int writeOut) {
    int idx = blockIdx.x * blockDim.x + threadIdx.x;   // (b,u) pairs: 512*16
    if (idx >= BB * US) return;
    int b = idx >> 4;
    int u = idx & 15;
    float sv[NU];
    float msq = 0.0f;
#pragma unroll
    for (int j = 0; j < NU; j++) {
        sv[j] = g_s[b * JU + j * US + u];
        msq += sv[j] * sv[j];
    }
    float mag = sqrtf(msq);
    float sc = msq / ((BETA + msq) * mag);
    if (writeOut) {
#pragma unroll
        for (int j = 0; j < NU; j++) out[b * JU + j * US + u] = sc * sv[j];
    } else {
#pragma unroll
        for (int j = 0; j < NU; j++) g_v[b * JU + j * US + u] = sc * sv[j];
    }
}

// GEMM2: G(9216 x 160) = x^T(9216 x 512) @ v(512 x 160), split over batch halves.
// Block tile 128(M over ki) x 160(N), 256 threads, micro 8x10, FFMA2.
__global__ __launch_bounds__(256, 2) void gemm2_k(const float* __restrict__ x) {
    __shared__ float As[16][MT];
    __shared__ float Bs[16][JU];
    const int m0 = blockIdx.x * MT;         // over KI
    const int kb0 = blockIdx.y * (BB / 2);  // batch half
    const int tid = threadIdx.x;
    const int trow = tid >> 4;
    const int tcol = tid & 15;

    unsigned long long acc[8][5];
#pragma unroll
    for (int r = 0; r < 8; r++)
#pragma unroll
        for (int c = 0; c < 5; c++) acc[r][c] = 0ULL;

    for (int kb = kb0; kb < kb0 + BB / 2; kb += 16) {
        // A tile: As[kk][m] = x[(kb+kk)*KI + m0+m]  (coalesced float4 copy)
#pragma unroll
        for (int l = 0; l < 2; l++) {
            int q = tid + l * 256;          // 512 float4 slots
            int kk = q >> 5;
            int m  = (q & 31) * 4;
            *reinterpret_cast<float4*>(&As[kk][m]) =
                *reinterpret_cast<const float4*>(&x[(kb + kk) * KI + m0 + m]);
        }
#pragma unroll
        for (int l = 0; l < 10; l++) {
            int idx = tid + l * 256;
            int kk = idx / 160;
            int n  = idx - kk * 160;
            Bs[kk][n] = g_v[(kb + kk) * JU + n];
        }
        __syncthreads();
#pragma unroll
        for (int kk = 0; kk < 16; kk++) {
            float4 a0 = *reinterpret_cast<const float4*>(&As[kk][trow * 8]);
            float4 a1 = *reinterpret_cast<const float4*>(&As[kk][trow * 8 + 4]);
            unsigned long long ap[8];
            ap[0] = pk2(a0.x); ap[1] = pk2(a0.y); ap[2] = pk2(a0.z); ap[3] = pk2(a0.w);
            ap[4] = pk2(a1.x); ap[5] = pk2(a1.y); ap[6] = pk2(a1.z); ap[7] = pk2(a1.w);
            unsigned long long bp[5];
#pragma unroll
            for (int c = 0; c < 5; c++)
                bp[c] = *reinterpret_cast<const unsigned long long*>(&Bs[kk][tcol * 10 + 2 * c]);
#pragma unroll
            for (int r = 0; r < 8; r++)
#pragma unroll
                for (int c = 0; c < 5; c++) ffma2(acc[r][c], ap[r], bp[c]);
        }
        __syncthreads();
    }

    float* out = g_Gpart[blockIdx.y];
#pragma unroll
    for (int r = 0; r < 8; r++)
#pragma unroll
        for (int c = 0; c < 5; c++)
            *reinterpret_cast<unsigned long long*>(
                &out[(m0 + trow * 8 + r) * JU + tcol * 10 + 2 * c]) = acc[r][c];
}

// b[i,j] = (1/B) * sum_{k,u} Wt[(k*INCH+i)*JU + j*US+u] * (G0+G1)[same]
__global__ void bupdate_k() {
    int gw = (blockIdx.x * blockDim.x + threadIdx.x) >> 5;
    int lane = threadIdx.x & 31;
    if (gw >= INCH * NU) return;
    int i = gw / NU;
    int j = gw - i * NU;
    int k = lane >> 2;
    int u = (lane & 3) * 4;
    int idx = (k * INCH + i) * JU + j * US + u;
    float4 w  = *reinterpret_cast<const float4*>(&g_Wt[idx]);
    float4 g0 = *reinterpret_cast<const float4*>(&g_Gpart[0][idx]);
    float4 g1 = *reinterpret_cast<const float4*>(&g_Gpart[1][idx]);
    float acc = w.x * (g0.x + g1.x) + w.y * (g0.y + g1.y)
              + w.z * (g0.z + g1.z) + w.w * (g0.w + g1.w);
#pragma unroll
    for (int o = 16; o > 0; o >>= 1) acc += __shfl_xor_sync(0xffffffffu, acc, o);
    if (lane == 0) g_b[i * NU + j] = acc * (1.0f / (float)BB);
}

// ---------------------------------------------------------------------------
extern "C" void kernel_launch(void* const* d_in, const int* in_sizes, int n_in,
                              void* d_out, int out_size) {
    const float* x = (const float*)d_in[0];
    const float* W = (const float*)d_in[1];
    if (n_in >= 2 && in_sizes[0] == INCH * NU * US * INU) {
        const float* t = x; x = W; W = t;
    }
    float* out = (float*)d_out;

    zero_b_k<<<(INCH * NU + 255) / 256, 256>>>();
    transposeW_k<<<(INCH * JU + 255) / 256, 256>>>(W);

    for (int t = 0; t < 3; t++) {
        softmax_k<<<NU, 128>>>();
        gemm1_k<<<dim3(BB / MT, KSPLIT), 256>>>(x);
        reduceS_k<<<(BB * JU / 4 + 255) / 256, 256>>>();
        squash_k<<<(BB * US + 255) / 256, 256>>>(out, t == 2 ? 1 : 0);
        if (t < 2) {
            gemm2_k<<<dim3(KI / MT, 2), 256>>>(x);
            bupdate_k<<<(INCH * NU * 32) / 256, 256>>>();
        }
    }
}